// round 1
// baseline (speedup 1.0000x reference)
#include <cuda_runtime.h>
#include <math.h>

#define C 256
#define NPOS 32768
#define NT 32
#define G 8
#define H 4
#define Dh 64

// scratch (static device allocations are allowed)
__device__ float g_Wq_t[C * C];          // q_w transposed [c][o]
__device__ float g_Wp_t[C * C];          // proj_w transposed [c][o]
__device__ float g_tokens[2 * C * G];    // [b][c][g]
__device__ float g_K[2 * H * Dh * G];    // [b][h][d][g], pre-scaled by 1/sqrt(d)
__device__ float g_V[2 * H * G * Dh];    // [b][h][g][d]

// ---------------------------------------------------------------------------
// Kernel A: transpose weights for broadcast-friendly access
// ---------------------------------------------------------------------------
__global__ void k_transpose(const float* __restrict__ q_w,
                            const float* __restrict__ proj_w) {
    int i = blockIdx.x * blockDim.x + threadIdx.x;  // 65536
    int o = i >> 8, c = i & 255;
    g_Wq_t[c * C + o] = q_w[o * C + c];
    g_Wp_t[c * C + o] = proj_w[o * C + c];
}

// ---------------------------------------------------------------------------
// Kernel B: adaptive avg pool 16^3 -> 2^3, depthwise 3x3x3 conv (SAME), add
// ---------------------------------------------------------------------------
__global__ void k_tokens(const float* __restrict__ x1,
                         const float* __restrict__ dw_w) {
    int bc = blockIdx.x;               // 0..511 = b*256 + c
    int c = bc & 255;
    const float* xp = x1 + (size_t)bc * 4096;
    int tid = threadIdx.x;             // 256
    int w = tid >> 5, lane = tid & 31; // warp w handles pooled cell g=w
    int gz = w >> 2, gy = (w >> 1) & 1, gx = w & 1;
    float s = 0.f;
#pragma unroll
    for (int k = 0; k < 16; k++) {
        int e = lane + 32 * k;         // 0..511 within 8x8x8 block
        int lz = e >> 6, ly = (e >> 3) & 7, lx = e & 7;
        s += xp[(gz * 8 + lz) * 256 + (gy * 8 + ly) * 16 + (gx * 8 + lx)];
    }
#pragma unroll
    for (int off = 16; off; off >>= 1) s += __shfl_down_sync(0xffffffffu, s, off);
    __shared__ float pooled[8];
    if (lane == 0) pooled[w] = s * (1.0f / 512.0f);
    __syncthreads();
    if (tid < 8) {
        int z = tid >> 2, y = (tid >> 1) & 1, x = tid & 1;
        float acc = 0.f;
        for (int dz = -1; dz <= 1; dz++)
            for (int dy = -1; dy <= 1; dy++)
                for (int dx = -1; dx <= 1; dx++) {
                    int nz = z + dz, ny = y + dy, nx = x + dx;
                    if ((unsigned)nz < 2u && (unsigned)ny < 2u && (unsigned)nx < 2u)
                        acc += dw_w[c * 27 + (dz + 1) * 9 + (dy + 1) * 3 + (dx + 1)] *
                               pooled[nz * 4 + ny * 2 + nx];
                }
        g_tokens[bc * 8 + tid] = pooled[tid] + acc;
    }
}

// ---------------------------------------------------------------------------
// Kernel C: LN over channels of tokens, K = k_w @ LN(tok) (scaled), V = v_w @ tok
// ---------------------------------------------------------------------------
__global__ void k_kv(const float* __restrict__ k_w, const float* __restrict__ v_w,
                     const float* __restrict__ nkv_w, const float* __restrict__ nkv_b) {
    int bg = blockIdx.x;               // 0..15 = b*8 + g
    int b = bg >> 3, g = bg & 7;
    int tid = threadIdx.x;             // 256 (one output channel each)
    __shared__ float tok[256], tk[256], red[16];
    __shared__ float uu, rstd;
    float t = g_tokens[(b * 256 + tid) * 8 + g];
    tok[tid] = t;
    float s1 = t, s2 = t * t;
#pragma unroll
    for (int off = 16; off; off >>= 1) {
        s1 += __shfl_down_sync(0xffffffffu, s1, off);
        s2 += __shfl_down_sync(0xffffffffu, s2, off);
    }
    int w = tid >> 5, lane = tid & 31;
    if (lane == 0) { red[w] = s1; red[8 + w] = s2; }
    __syncthreads();
    if (tid == 0) {
        float a = 0.f, q = 0.f;
        for (int i = 0; i < 8; i++) { a += red[i]; q += red[8 + i]; }
        float u = a * (1.0f / 256.0f);
        float var = q * (1.0f / 256.0f) - u * u;
        uu = u; rstd = rsqrtf(var + 1e-6f);
    }
    __syncthreads();
    tk[tid] = (t - uu) * rstd * nkv_w[tid] + nkv_b[tid];
    __syncthreads();
    float ko = 0.f, vo = 0.f;
    const float* kr = k_w + tid * 256;
    const float* vr = v_w + tid * 256;
    for (int c2 = 0; c2 < 256; c2++) { ko += kr[c2] * tk[c2]; vo += vr[c2] * tok[c2]; }
    int h = tid >> 6, d = tid & 63;
    g_K[((b * 4 + h) * 64 + d) * 8 + g] = ko * 0.125f;   // fold 1/sqrt(64)
    g_V[((b * 4 + h) * 8 + g) * 64 + d] = vo;
}

// ---------------------------------------------------------------------------
// Kernel D: fused LN(x2) -> Q -> attention(g=8) -> out-proj, 32 positions/block
// smem: Xs[256][32] | Th[64][32] | Kh[4][64][8] | Vh[4][8][64] | Sc[8][32] | red[512]
// ---------------------------------------------------------------------------
#define SMEM_FLOATS (256 * 32 + 64 * 32 + 2048 + 2048 + 256 + 512)

__global__ void __launch_bounds__(256) k_main(
    const float* __restrict__ x2, const float* __restrict__ nq_w,
    const float* __restrict__ nq_b, float* __restrict__ out) {
    extern __shared__ float sm[];
    float* Xs = sm;                 // 8192
    float* Th = Xs + 256 * 32;      // 2048
    float* Kh = Th + 64 * 32;       // 2048
    float* Vh = Kh + 2048;          // 2048
    float* Sc = Vh + 2048;          // 256
    float* red = Sc + 256;          // 512
    __shared__ float u_s[32], r_s[32];

    int bid = blockIdx.x;           // 0..2047
    int b = bid >> 10;
    int n0 = (bid & 1023) * NT;
    int tid = threadIdx.x;
    int wg = tid >> 5, lane = tid & 31;

    const float* xb = x2 + (size_t)b * C * NPOS;
    for (int i = tid; i < 256 * 32; i += 256) {
        int cc = i >> 5, nn = i & 31;
        Xs[i] = xb[(size_t)cc * NPOS + n0 + nn];
    }
    for (int i = tid; i < 2048; i += 256) {
        Kh[i] = g_K[b * 2048 + i];
        Vh[i] = g_V[b * 2048 + i];
    }
    __syncthreads();

    // LayerNorm over C per column
    {
        float s1 = 0.f, s2 = 0.f;
#pragma unroll
        for (int k = 0; k < 32; k++) {
            float v = Xs[(wg * 32 + k) * 32 + lane];
            s1 += v; s2 += v * v;
        }
        red[wg * 32 + lane] = s1;
        red[256 + wg * 32 + lane] = s2;
    }
    __syncthreads();
    if (tid < 32) {
        float a = 0.f, q = 0.f;
#pragma unroll
        for (int w = 0; w < 8; w++) { a += red[w * 32 + tid]; q += red[256 + w * 32 + tid]; }
        float u = a * (1.0f / 256.0f);
        float var = q * (1.0f / 256.0f) - u * u;
        u_s[tid] = u; r_s[tid] = rsqrtf(var + 1e-6f);
    }
    __syncthreads();
    {
        float u = u_s[lane], r = r_s[lane];
#pragma unroll
        for (int k = 0; k < 32; k++) {
            int cc = wg * 32 + k;
            Xs[cc * 32 + lane] = (Xs[cc * 32 + lane] - u) * r * nq_w[cc] + nq_b[cc];
        }
    }
    __syncthreads();

    float y[32];
#pragma unroll
    for (int j = 0; j < 32; j++) y[j] = 0.f;

    for (int hh = 0; hh < 4; hh++) {
        // ---- Q GEMM: thread (wg, lane) computes d = wg*8 .. wg*8+7 for column lane
        float acc[8];
#pragma unroll
        for (int j = 0; j < 8; j++) acc[j] = 0.f;
        const float4* Wq = reinterpret_cast<const float4*>(g_Wq_t + hh * 64 + wg * 8);
        for (int cc = 0; cc < 256; cc++) {
            float xv = Xs[cc * 32 + lane];
            float4 w0 = Wq[cc * 64];
            float4 w1 = Wq[cc * 64 + 1];
            acc[0] += w0.x * xv; acc[1] += w0.y * xv; acc[2] += w0.z * xv; acc[3] += w0.w * xv;
            acc[4] += w1.x * xv; acc[5] += w1.y * xv; acc[6] += w1.z * xv; acc[7] += w1.w * xv;
        }
#pragma unroll
        for (int j = 0; j < 8; j++) Th[(wg * 8 + j) * 32 + lane] = acc[j];
        __syncthreads();

        // ---- scores: thread (g=wg, n=lane), K pre-scaled
        {
            float s = 0.f;
            const float* kp = Kh + hh * 512 + wg;    // [hh][d][g]
#pragma unroll
            for (int d = 0; d < 64; d++) s += Th[d * 32 + lane] * kp[d * 8];
            Sc[wg * 32 + lane] = s;
        }
        __syncthreads();

        // ---- softmax over g=8 (one column per thread, warp 0)
        if (tid < 32) {
            float m = -1e30f;
#pragma unroll
            for (int g2 = 0; g2 < 8; g2++) m = fmaxf(m, Sc[g2 * 32 + tid]);
            float e[8]; float ssum = 0.f;
#pragma unroll
            for (int g2 = 0; g2 < 8; g2++) { e[g2] = expf(Sc[g2 * 32 + tid] - m); ssum += e[g2]; }
            float inv = 1.0f / ssum;
#pragma unroll
            for (int g2 = 0; g2 < 8; g2++) Sc[g2 * 32 + tid] = e[g2] * inv;
        }
        __syncthreads();

        // ---- out_h = attn @ V : d = wg*8+j for column lane
        float acc2[8];
#pragma unroll
        for (int j = 0; j < 8; j++) acc2[j] = 0.f;
#pragma unroll
        for (int g2 = 0; g2 < 8; g2++) {
            float av = Sc[g2 * 32 + lane];
            const float* vp = Vh + hh * 512 + g2 * 64 + wg * 8;
#pragma unroll
            for (int j = 0; j < 8; j++) acc2[j] += av * vp[j];
        }
#pragma unroll
        for (int j = 0; j < 8; j++) Th[(wg * 8 + j) * 32 + lane] = acc2[j];
        __syncthreads();

        // ---- proj accumulate: o = wg*32 + k over this head's 64 channels
        for (int d = 0; d < 64; d++) {
            float ov = Th[d * 32 + lane];
            int cc = hh * 64 + d;
            const float4* wrow = reinterpret_cast<const float4*>(g_Wp_t + cc * 256 + wg * 32);
#pragma unroll
            for (int k4 = 0; k4 < 8; k4++) {
                float4 w = wrow[k4];
                y[k4 * 4 + 0] += w.x * ov; y[k4 * 4 + 1] += w.y * ov;
                y[k4 * 4 + 2] += w.z * ov; y[k4 * 4 + 3] += w.w * ov;
            }
        }
        __syncthreads();   // Th reused next head
    }

    float* ob = out + (size_t)b * C * NPOS + n0 + lane;
#pragma unroll
    for (int j = 0; j < 32; j++) {
        ob[(size_t)(wg * 32 + j) * NPOS] = y[j];
    }
}

// ---------------------------------------------------------------------------
extern "C" void kernel_launch(void* const* d_in, const int* in_sizes, int n_in,
                              void* d_out, int out_size) {
    const float* x2     = (const float*)d_in[0];
    const float* x1_low = (const float*)d_in[1];
    const float* q_w    = (const float*)d_in[2];
    const float* k_w    = (const float*)d_in[3];
    const float* v_w    = (const float*)d_in[4];
    const float* dw_w   = (const float*)d_in[5];
    const float* proj_w = (const float*)d_in[6];
    const float* nq_w   = (const float*)d_in[7];
    const float* nq_b   = (const float*)d_in[8];
    const float* nkv_w  = (const float*)d_in[9];
    const float* nkv_b  = (const float*)d_in[10];
    float* out = (float*)d_out;

    cudaFuncSetAttribute(k_main, cudaFuncAttributeMaxDynamicSharedMemorySize,
                         SMEM_FLOATS * sizeof(float));

    k_transpose<<<256, 256>>>(q_w, proj_w);
    k_tokens<<<512, 256>>>(x1_low, dw_w);
    k_kv<<<16, 256>>>(k_w, v_w, nkv_w, nkv_b);
    k_main<<<2048, 256, SMEM_FLOATS * sizeof(float)>>>(x2, nq_w, nq_b, out);
}

// round 2
// speedup vs baseline: 1.0002x; 1.0002x over previous
#include <cuda_runtime.h>
#include <math.h>

#define C 256
#define NPOS 32768
#define NT 32
#define G 8
#define H 4
#define Dh 64

// scratch (static device allocations are allowed)
__device__ float g_Wq_t[C * C];          // q_w transposed [c][o]
__device__ float g_Wp_t[C * C];          // proj_w transposed [c][o]
__device__ float g_tokens[2 * C * G];    // [b][c][g]
__device__ float g_K[2 * H * Dh * G];    // [b][h][d][g], pre-scaled by 1/sqrt(d)
__device__ float g_V[2 * H * G * Dh];    // [b][h][g][d]

// ---------------------------------------------------------------------------
// Kernel A: transpose weights for broadcast-friendly access
// ---------------------------------------------------------------------------
__global__ void k_transpose(const float* __restrict__ q_w,
                            const float* __restrict__ proj_w) {
    int i = blockIdx.x * blockDim.x + threadIdx.x;  // 65536
    int o = i >> 8, c = i & 255;
    g_Wq_t[c * C + o] = q_w[o * C + c];
    g_Wp_t[c * C + o] = proj_w[o * C + c];
}

// ---------------------------------------------------------------------------
// Kernel B: adaptive avg pool 16^3 -> 2^3, depthwise 3x3x3 conv (SAME), add
// ---------------------------------------------------------------------------
__global__ void k_tokens(const float* __restrict__ x1,
                         const float* __restrict__ dw_w) {
    int bc = blockIdx.x;               // 0..511 = b*256 + c
    int c = bc & 255;
    const float* xp = x1 + (size_t)bc * 4096;
    int tid = threadIdx.x;             // 256
    int w = tid >> 5, lane = tid & 31; // warp w handles pooled cell g=w
    int gz = w >> 2, gy = (w >> 1) & 1, gx = w & 1;
    float s = 0.f;
#pragma unroll
    for (int k = 0; k < 16; k++) {
        int e = lane + 32 * k;         // 0..511 within 8x8x8 block
        int lz = e >> 6, ly = (e >> 3) & 7, lx = e & 7;
        s += xp[(gz * 8 + lz) * 256 + (gy * 8 + ly) * 16 + (gx * 8 + lx)];
    }
#pragma unroll
    for (int off = 16; off; off >>= 1) s += __shfl_down_sync(0xffffffffu, s, off);
    __shared__ float pooled[8];
    if (lane == 0) pooled[w] = s * (1.0f / 512.0f);
    __syncthreads();
    if (tid < 8) {
        int z = tid >> 2, y = (tid >> 1) & 1, x = tid & 1;
        float acc = 0.f;
        for (int dz = -1; dz <= 1; dz++)
            for (int dy = -1; dy <= 1; dy++)
                for (int dx = -1; dx <= 1; dx++) {
                    int nz = z + dz, ny = y + dy, nx = x + dx;
                    if ((unsigned)nz < 2u && (unsigned)ny < 2u && (unsigned)nx < 2u)
                        acc += dw_w[c * 27 + (dz + 1) * 9 + (dy + 1) * 3 + (dx + 1)] *
                               pooled[nz * 4 + ny * 2 + nx];
                }
        g_tokens[bc * 8 + tid] = pooled[tid] + acc;
    }
}

// ---------------------------------------------------------------------------
// Kernel C: LN over channels of tokens, K = k_w @ LN(tok) (scaled), V = v_w @ tok
// ---------------------------------------------------------------------------
__global__ void k_kv(const float* __restrict__ k_w, const float* __restrict__ v_w,
                     const float* __restrict__ nkv_w, const float* __restrict__ nkv_b) {
    int bg = blockIdx.x;               // 0..15 = b*8 + g
    int b = bg >> 3, g = bg & 7;
    int tid = threadIdx.x;             // 256 (one output channel each)
    __shared__ float tok[256], tk[256], red[16];
    __shared__ float uu, rstd;
    float t = g_tokens[(b * 256 + tid) * 8 + g];
    tok[tid] = t;
    float s1 = t, s2 = t * t;
#pragma unroll
    for (int off = 16; off; off >>= 1) {
        s1 += __shfl_down_sync(0xffffffffu, s1, off);
        s2 += __shfl_down_sync(0xffffffffu, s2, off);
    }
    int w = tid >> 5, lane = tid & 31;
    if (lane == 0) { red[w] = s1; red[8 + w] = s2; }
    __syncthreads();
    if (tid == 0) {
        float a = 0.f, q = 0.f;
        for (int i = 0; i < 8; i++) { a += red[i]; q += red[8 + i]; }
        float u = a * (1.0f / 256.0f);
        float var = q * (1.0f / 256.0f) - u * u;
        uu = u; rstd = rsqrtf(var + 1e-6f);
    }
    __syncthreads();
    tk[tid] = (t - uu) * rstd * nkv_w[tid] + nkv_b[tid];
    __syncthreads();
    float ko = 0.f, vo = 0.f;
    const float* kr = k_w + tid * 256;
    const float* vr = v_w + tid * 256;
    for (int c2 = 0; c2 < 256; c2++) { ko += kr[c2] * tk[c2]; vo += vr[c2] * tok[c2]; }
    int h = tid >> 6, d = tid & 63;
    g_K[((b * 4 + h) * 64 + d) * 8 + g] = ko * 0.125f;   // fold 1/sqrt(64)
    g_V[((b * 4 + h) * 8 + g) * 64 + d] = vo;
}

// ---------------------------------------------------------------------------
// Kernel D: fused LN(x2) -> Q -> attention(g=8) -> out-proj, 32 positions/block
// smem: Xs[256][32] | Th[64][32] | Kh[4][64][8] | Vh[4][8][64] | Sc[8][32] | red[512]
// ---------------------------------------------------------------------------
#define SMEM_FLOATS (256 * 32 + 64 * 32 + 2048 + 2048 + 256 + 512)

__global__ void __launch_bounds__(256) k_main(
    const float* __restrict__ x2, const float* __restrict__ nq_w,
    const float* __restrict__ nq_b, float* __restrict__ out) {
    extern __shared__ float sm[];
    float* Xs = sm;                 // 8192
    float* Th = Xs + 256 * 32;      // 2048
    float* Kh = Th + 64 * 32;       // 2048
    float* Vh = Kh + 2048;          // 2048
    float* Sc = Vh + 2048;          // 256
    float* red = Sc + 256;          // 512
    __shared__ float u_s[32], r_s[32];

    int bid = blockIdx.x;           // 0..2047
    int b = bid >> 10;
    int n0 = (bid & 1023) * NT;
    int tid = threadIdx.x;
    int wg = tid >> 5, lane = tid & 31;

    const float* xb = x2 + (size_t)b * C * NPOS;
    for (int i = tid; i < 256 * 32; i += 256) {
        int cc = i >> 5, nn = i & 31;
        Xs[i] = xb[(size_t)cc * NPOS + n0 + nn];
    }
    for (int i = tid; i < 2048; i += 256) {
        Kh[i] = g_K[b * 2048 + i];
        Vh[i] = g_V[b * 2048 + i];
    }
    __syncthreads();

    // LayerNorm over C per column
    {
        float s1 = 0.f, s2 = 0.f;
#pragma unroll
        for (int k = 0; k < 32; k++) {
            float v = Xs[(wg * 32 + k) * 32 + lane];
            s1 += v; s2 += v * v;
        }
        red[wg * 32 + lane] = s1;
        red[256 + wg * 32 + lane] = s2;
    }
    __syncthreads();
    if (tid < 32) {
        float a = 0.f, q = 0.f;
#pragma unroll
        for (int w = 0; w < 8; w++) { a += red[w * 32 + tid]; q += red[256 + w * 32 + tid]; }
        float u = a * (1.0f / 256.0f);
        float var = q * (1.0f / 256.0f) - u * u;
        u_s[tid] = u; r_s[tid] = rsqrtf(var + 1e-6f);
    }
    __syncthreads();
    {
        float u = u_s[lane], r = r_s[lane];
#pragma unroll
        for (int k = 0; k < 32; k++) {
            int cc = wg * 32 + k;
            Xs[cc * 32 + lane] = (Xs[cc * 32 + lane] - u) * r * nq_w[cc] + nq_b[cc];
        }
    }
    __syncthreads();

    float y[32];
#pragma unroll
    for (int j = 0; j < 32; j++) y[j] = 0.f;

    for (int hh = 0; hh < 4; hh++) {
        // ---- Q GEMM: thread (wg, lane) computes d = wg*8 .. wg*8+7 for column lane
        float acc[8];
#pragma unroll
        for (int j = 0; j < 8; j++) acc[j] = 0.f;
        const float4* Wq = reinterpret_cast<const float4*>(g_Wq_t + hh * 64 + wg * 8);
        for (int cc = 0; cc < 256; cc++) {
            float xv = Xs[cc * 32 + lane];
            float4 w0 = Wq[cc * 64];
            float4 w1 = Wq[cc * 64 + 1];
            acc[0] += w0.x * xv; acc[1] += w0.y * xv; acc[2] += w0.z * xv; acc[3] += w0.w * xv;
            acc[4] += w1.x * xv; acc[5] += w1.y * xv; acc[6] += w1.z * xv; acc[7] += w1.w * xv;
        }
#pragma unroll
        for (int j = 0; j < 8; j++) Th[(wg * 8 + j) * 32 + lane] = acc[j];
        __syncthreads();

        // ---- scores: thread (g=wg, n=lane), K pre-scaled
        {
            float s = 0.f;
            const float* kp = Kh + hh * 512 + wg;    // [hh][d][g]
#pragma unroll
            for (int d = 0; d < 64; d++) s += Th[d * 32 + lane] * kp[d * 8];
            Sc[wg * 32 + lane] = s;
        }
        __syncthreads();

        // ---- softmax over g=8 (one column per thread, warp 0)
        if (tid < 32) {
            float m = -1e30f;
#pragma unroll
            for (int g2 = 0; g2 < 8; g2++) m = fmaxf(m, Sc[g2 * 32 + tid]);
            float e[8]; float ssum = 0.f;
#pragma unroll
            for (int g2 = 0; g2 < 8; g2++) { e[g2] = expf(Sc[g2 * 32 + tid] - m); ssum += e[g2]; }
            float inv = 1.0f / ssum;
#pragma unroll
            for (int g2 = 0; g2 < 8; g2++) Sc[g2 * 32 + tid] = e[g2] * inv;
        }
        __syncthreads();

        // ---- out_h = attn @ V : d = wg*8+j for column lane
        float acc2[8];
#pragma unroll
        for (int j = 0; j < 8; j++) acc2[j] = 0.f;
#pragma unroll
        for (int g2 = 0; g2 < 8; g2++) {
            float av = Sc[g2 * 32 + lane];
            const float* vp = Vh + hh * 512 + g2 * 64 + wg * 8;
#pragma unroll
            for (int j = 0; j < 8; j++) acc2[j] += av * vp[j];
        }
#pragma unroll
        for (int j = 0; j < 8; j++) Th[(wg * 8 + j) * 32 + lane] = acc2[j];
        __syncthreads();

        // ---- proj accumulate: o = wg*32 + k over this head's 64 channels
        for (int d = 0; d < 64; d++) {
            float ov = Th[d * 32 + lane];
            int cc = hh * 64 + d;
            const float4* wrow = reinterpret_cast<const float4*>(g_Wp_t + cc * 256 + wg * 32);
#pragma unroll
            for (int k4 = 0; k4 < 8; k4++) {
                float4 w = wrow[k4];
                y[k4 * 4 + 0] += w.x * ov; y[k4 * 4 + 1] += w.y * ov;
                y[k4 * 4 + 2] += w.z * ov; y[k4 * 4 + 3] += w.w * ov;
            }
        }
        __syncthreads();   // Th reused next head
    }

    float* ob = out + (size_t)b * C * NPOS + n0 + lane;
#pragma unroll
    for (int j = 0; j < 32; j++) {
        ob[(size_t)(wg * 32 + j) * NPOS] = y[j];
    }
}

// ---------------------------------------------------------------------------
extern "C" void kernel_launch(void* const* d_in, const int* in_sizes, int n_in,
                              void* d_out, int out_size) {
    const float* x2     = (const float*)d_in[0];
    const float* x1_low = (const float*)d_in[1];
    const float* q_w    = (const float*)d_in[2];
    const float* k_w    = (const float*)d_in[3];
    const float* v_w    = (const float*)d_in[4];
    const float* dw_w   = (const float*)d_in[5];
    const float* proj_w = (const float*)d_in[6];
    const float* nq_w   = (const float*)d_in[7];
    const float* nq_b   = (const float*)d_in[8];
    const float* nkv_w  = (const float*)d_in[9];
    const float* nkv_b  = (const float*)d_in[10];
    float* out = (float*)d_out;

    cudaFuncSetAttribute(k_main, cudaFuncAttributeMaxDynamicSharedMemorySize,
                         SMEM_FLOATS * sizeof(float));

    k_transpose<<<256, 256>>>(q_w, proj_w);
    k_tokens<<<512, 256>>>(x1_low, dw_w);
    k_kv<<<16, 256>>>(k_w, v_w, nkv_w, nkv_b);
    k_main<<<2048, 256, SMEM_FLOATS * sizeof(float)>>>(x2, nq_w, nq_b, out);
}

// round 3
// speedup vs baseline: 2.6347x; 2.6342x over previous
#include <cuda_runtime.h>
#include <math.h>

#define C 256
#define NPOS 32768
#define G 8
#define H 4

typedef unsigned long long u64;

// ---- scratch --------------------------------------------------------------
__device__ float g_tokens[2 * C * G];     // [b][c][g]
__device__ float g_K[2 * H * 64 * G];     // [b][h][d][g], pre-scaled by 1/8
__device__ float g_V[2 * H * G * 64];     // [b][h][g][d]
__device__ float g_Ms[2 * C * 32];        // [b][c][hg]  raw folded score matrix
__device__ float g_P[2 * 32 * C];         // [b][hg][o]  folded output matrix
__device__ float g_cs[2 * 32];            // colsum of Ms*nq_w
__device__ float g_bias[2 * 32];          // Ms . nq_b

// ---- f32x2 helpers ----------------------------------------------------------
__device__ __forceinline__ u64 dup2(float a) {
    u64 r; asm("mov.b64 %0,{%1,%1};" : "=l"(r) : "f"(a)); return r;
}
__device__ __forceinline__ u64 pack2(float a, float b) {
    u64 r; asm("mov.b64 %0,{%1,%2};" : "=l"(r) : "f"(a), "f"(b)); return r;
}
__device__ __forceinline__ u64 ffma2(u64 a, u64 b, u64 c) {
    u64 d; asm("fma.rn.f32x2 %0,%1,%2,%3;" : "=l"(d) : "l"(a), "l"(b), "l"(c)); return d;
}
__device__ __forceinline__ u64 add2(u64 a, u64 b) {
    u64 d; asm("add.rn.f32x2 %0,%1,%2;" : "=l"(d) : "l"(a), "l"(b)); return d;
}
__device__ __forceinline__ float lo2(u64 v) { return __uint_as_float((unsigned)v); }
__device__ __forceinline__ float hi2(u64 v) { return __uint_as_float((unsigned)(v >> 32)); }

__device__ __forceinline__ void cpa16(unsigned s, const void* g) {
    asm volatile("cp.async.cg.shared.global [%0], [%1], 16;" :: "r"(s), "l"(g));
}
__device__ __forceinline__ void cpa_commit() { asm volatile("cp.async.commit_group;"); }
__device__ __forceinline__ void cpa_wait1() { asm volatile("cp.async.wait_group 1;"); }
__device__ __forceinline__ void cpa_wait0() { asm volatile("cp.async.wait_group 0;"); }

// ---------------------------------------------------------------------------
// pool 16^3 -> 2^3 + depthwise 3^3 conv (SAME) + residual
// ---------------------------------------------------------------------------
__global__ void k_tokens(const float* __restrict__ x1,
                         const float* __restrict__ dw_w) {
    int bc = blockIdx.x;               // b*256 + c
    int c = bc & 255;
    const float* xp = x1 + (size_t)bc * 4096;
    int tid = threadIdx.x;
    int w = tid >> 5, lane = tid & 31;
    int gz = w >> 2, gy = (w >> 1) & 1, gx = w & 1;
    float s = 0.f;
#pragma unroll
    for (int k = 0; k < 16; k++) {
        int e = lane + 32 * k;
        int lz = e >> 6, ly = (e >> 3) & 7, lx = e & 7;
        s += xp[(gz * 8 + lz) * 256 + (gy * 8 + ly) * 16 + (gx * 8 + lx)];
    }
#pragma unroll
    for (int off = 16; off; off >>= 1) s += __shfl_down_sync(0xffffffffu, s, off);
    __shared__ float pooled[8];
    if (lane == 0) pooled[w] = s * (1.0f / 512.0f);
    __syncthreads();
    if (tid < 8) {
        int z = tid >> 2, y = (tid >> 1) & 1, x = tid & 1;
        float acc = 0.f;
        for (int dz = -1; dz <= 1; dz++)
            for (int dy = -1; dy <= 1; dy++)
                for (int dx = -1; dx <= 1; dx++) {
                    int nz = z + dz, ny = y + dy, nx = x + dx;
                    if ((unsigned)nz < 2u && (unsigned)ny < 2u && (unsigned)nx < 2u)
                        acc += dw_w[c * 27 + (dz + 1) * 9 + (dy + 1) * 3 + (dx + 1)] *
                               pooled[nz * 4 + ny * 2 + nx];
                }
        g_tokens[bc * 8 + tid] = pooled[tid] + acc;
    }
}

// ---------------------------------------------------------------------------
// LN(tokens) over channels, K (prescaled), V
// ---------------------------------------------------------------------------
__global__ void k_kv(const float* __restrict__ k_w, const float* __restrict__ v_w,
                     const float* __restrict__ nkv_w, const float* __restrict__ nkv_b) {
    int bg = blockIdx.x;               // b*8 + g
    int b = bg >> 3, g = bg & 7;
    int tid = threadIdx.x;             // 256
    __shared__ float tok[256], tk[256], red[16];
    __shared__ float uu, rstd;
    float t = g_tokens[(b * 256 + tid) * 8 + g];
    tok[tid] = t;
    float s1 = t, s2 = t * t;
#pragma unroll
    for (int off = 16; off; off >>= 1) {
        s1 += __shfl_down_sync(0xffffffffu, s1, off);
        s2 += __shfl_down_sync(0xffffffffu, s2, off);
    }
    int w = tid >> 5, lane = tid & 31;
    if (lane == 0) { red[w] = s1; red[8 + w] = s2; }
    __syncthreads();
    if (tid == 0) {
        float a = 0.f, q = 0.f;
        for (int i = 0; i < 8; i++) { a += red[i]; q += red[8 + i]; }
        float u = a * (1.0f / 256.0f);
        float var = q * (1.0f / 256.0f) - u * u;
        uu = u; rstd = rsqrtf(var + 1e-6f);
    }
    __syncthreads();
    tk[tid] = (t - uu) * rstd * nkv_w[tid] + nkv_b[tid];
    __syncthreads();
    float ko = 0.f, vo = 0.f;
    const float* kr = k_w + tid * 256;
    const float* vr = v_w + tid * 256;
    for (int c2 = 0; c2 < 256; c2++) { ko += kr[c2] * tk[c2]; vo += vr[c2] * tok[c2]; }
    int h = tid >> 6, d = tid & 63;
    g_K[((b * 4 + h) * 64 + d) * 8 + g] = ko * 0.125f;
    g_V[((b * 4 + h) * 8 + g) * 64 + d] = vo;
}

// ---------------------------------------------------------------------------
// fold: Ms[c][hg] = sum_d q_w[h*64+d, c] * K[h,d,g] ; P[hg][o] = sum_d proj_w[o, h*64+d] * V[h,g,d]
// ---------------------------------------------------------------------------
__global__ void k_fold(const float* __restrict__ q_w,
                       const float* __restrict__ proj_w) {
    int b = blockIdx.x;
    int t = threadIdx.x;               // 256 : c for Ms, o for P
    for (int h = 0; h < 4; h++)
        for (int g = 0; g < 8; g++) {
            float s = 0.f;
            const float* kk = g_K + ((b * 4 + h) * 64) * 8 + g;
#pragma unroll 8
            for (int d = 0; d < 64; d++)
                s += q_w[((h * 64 + d) << 8) + t] * kk[d * 8];
            g_Ms[(b * 256 + t) * 32 + h * 8 + g] = s;
        }
    for (int h = 0; h < 4; h++)
        for (int g = 0; g < 8; g++) {
            float s = 0.f;
            const float* pw = proj_w + t * 256 + h * 64;
            const float* vv = g_V + ((b * 4 + h) * 8 + g) * 64;
#pragma unroll 8
            for (int d = 0; d < 64; d++) s += pw[d] * vv[d];
            g_P[b * 8192 + (h * 8 + g) * 256 + t] = s;
        }
}

__global__ void k_fold2(const float* __restrict__ nq_w,
                        const float* __restrict__ nq_b) {
    int b = blockIdx.x;
    int hg = threadIdx.x;              // 32
    float cs = 0.f, bs = 0.f;
    for (int c = 0; c < 256; c++) {
        float m = g_Ms[(b * 256 + c) * 32 + hg];
        cs += nq_w[c] * m;
        bs += nq_b[c] * m;
    }
    g_cs[b * 32 + hg] = cs;
    g_bias[b * 32 + hg] = bs;
}

// ---------------------------------------------------------------------------
// main fused kernel: 256 positions/block, 256 threads
// thread: j = tid&127 owns positions (j, j+128); og = tid>>7 owns score
// channels [og*16, og*16+16) (8 f32x2 pairs).
// ---------------------------------------------------------------------------
#define SM_MSP 0
#define SM_P   8192
#define SM_X   16384          /* 2 bufs x 8192 floats */
#define SM_S   32768
#define SM_RED 40960          /* 512 u64 = 1024 floats */
#define SM_US  41984
#define SM_RS  42240
#define SM_CSB 42496          /* cs[32] bias[32] */
#define SM_TOT 42560

__global__ void __launch_bounds__(256, 1) k_main(
    const float* __restrict__ x2, const float* __restrict__ nq_w,
    float* __restrict__ out) {
    extern __shared__ float sm[];
    int tid = threadIdx.x;
    int j = tid & 127, og = tid >> 7;
    int b = blockIdx.x >> 7;
    int n0 = (blockIdx.x & 127) * 256;

    // load folded weights
    for (int i = tid; i < 8192; i += 256) {
        sm[SM_MSP + i] = g_Ms[b * 8192 + i] * nq_w[i >> 5];
        sm[SM_P + i]   = g_P[b * 8192 + i];
    }
    if (tid < 32) {
        sm[SM_CSB + tid]      = g_cs[b * 32 + tid];
        sm[SM_CSB + 32 + tid] = g_bias[b * 32 + tid];
    }

    const float* xb = x2 + (size_t)b * C * NPOS + n0;
    unsigned xs_u32 = (unsigned)__cvta_generic_to_shared(sm + SM_X);

    // prologue: chunk 0
    {
        const float* src = xb;
#pragma unroll
        for (int it = 0; it < 8; it++) {
            int idx = tid + it * 256;
            int row = idx >> 6, col = idx & 63;
            cpa16(xs_u32 + (unsigned)(row * 1024 + col * 16),
                  src + (size_t)row * NPOS + col * 4);
        }
        cpa_commit();
    }

    u64 acc0[8], acc1[8], s1p = 0ull, s2p = 0ull;
#pragma unroll
    for (int k = 0; k < 8; k++) { acc0[k] = 0ull; acc1[k] = 0ull; }

    for (int ch = 0; ch < 8; ch++) {
        if (ch < 7) {
            const float* src = xb + (size_t)((ch + 1) * 32) * NPOS;
            unsigned dst = xs_u32 + ((unsigned)((ch + 1) & 1)) * 32768u;
#pragma unroll
            for (int it = 0; it < 8; it++) {
                int idx = tid + it * 256;
                int row = idx >> 6, col = idx & 63;
                cpa16(dst + (unsigned)(row * 1024 + col * 16),
                      src + (size_t)row * NPOS + col * 4);
            }
            cpa_commit();
            cpa_wait1();
        } else {
            cpa_wait0();
        }
        __syncthreads();

        const float* Xc = sm + SM_X + ((ch & 1) << 13);
        bool dostats = (og == (ch >> 2));
#pragma unroll 8
        for (int cl = 0; cl < 32; cl++) {
            float x0 = Xc[cl * 256 + j];
            float x1 = Xc[cl * 256 + j + 128];
            u64 x0d = dup2(x0), x1d = dup2(x1);
            const ulonglong2* wq = reinterpret_cast<const ulonglong2*>(
                sm + SM_MSP + (ch * 32 + cl) * 32 + og * 16);
#pragma unroll
            for (int pr = 0; pr < 4; pr++) {
                ulonglong2 w = wq[pr];
                acc0[pr * 2]     = ffma2(w.x, x0d, acc0[pr * 2]);
                acc0[pr * 2 + 1] = ffma2(w.y, x0d, acc0[pr * 2 + 1]);
                acc1[pr * 2]     = ffma2(w.x, x1d, acc1[pr * 2]);
                acc1[pr * 2 + 1] = ffma2(w.y, x1d, acc1[pr * 2 + 1]);
            }
            if (dostats) {
                u64 xp = pack2(x0, x1);
                s1p = add2(s1p, xp);
                s2p = ffma2(xp, xp, s2p);
            }
        }
        __syncthreads();
    }

    // ---- reduce LN stats (p0 in lo lane, p1 in hi lane)
    u64* redm = reinterpret_cast<u64*>(sm + SM_RED);
    redm[(og * 128 + j) * 2]     = s1p;
    redm[(og * 128 + j) * 2 + 1] = s2p;
    __syncthreads();
    if (og == 0) {
        u64 s1t = add2(redm[j * 2], redm[(128 + j) * 2]);
        u64 s2t = add2(redm[j * 2 + 1], redm[(128 + j) * 2 + 1]);
        float u0 = lo2(s1t) * (1.0f / 256.0f), u1 = hi2(s1t) * (1.0f / 256.0f);
        float v0 = lo2(s2t) * (1.0f / 256.0f) - u0 * u0;
        float v1 = hi2(s2t) * (1.0f / 256.0f) - u1 * u1;
        sm[SM_US + j] = u0;       sm[SM_US + j + 128] = u1;
        sm[SM_RS + j] = rsqrtf(v0 + 1e-6f);
        sm[SM_RS + j + 128] = rsqrtf(v1 + 1e-6f);
    }
    __syncthreads();

    // ---- correct scores, write S[hg][pos]
    {
        u64 nu0 = dup2(-sm[SM_US + j]);
        u64 nu1 = dup2(-sm[SM_US + j + 128]);
        u64 r0  = dup2(sm[SM_RS + j]);
        u64 r1  = dup2(sm[SM_RS + j + 128]);
        const u64* csb = reinterpret_cast<const u64*>(sm + SM_CSB);
#pragma unroll
        for (int oo = 0; oo < 8; oo++) {
            int o = og * 16 + oo * 2;
            u64 cs2 = csb[o >> 1];
            u64 b2  = csb[16 + (o >> 1)];
            u64 t0 = ffma2(cs2, nu0, acc0[oo]);
            u64 sc0 = ffma2(t0, r0, b2);
            u64 t1 = ffma2(cs2, nu1, acc1[oo]);
            u64 sc1 = ffma2(t1, r1, b2);
            sm[SM_S + o * 256 + j]             = lo2(sc0);
            sm[SM_S + (o + 1) * 256 + j]       = hi2(sc0);
            sm[SM_S + o * 256 + j + 128]       = lo2(sc1);
            sm[SM_S + (o + 1) * 256 + j + 128] = hi2(sc1);
        }
    }
    __syncthreads();

    // ---- softmax: thread = position, 4 heads x 8 keys
    {
        int p = tid;
#pragma unroll
        for (int h = 0; h < 4; h++) {
            float v[8], m = -1e30f;
#pragma unroll
            for (int g = 0; g < 8; g++) {
                v[g] = sm[SM_S + (h * 8 + g) * 256 + p];
                m = fmaxf(m, v[g]);
            }
            float ssum = 0.f;
#pragma unroll
            for (int g = 0; g < 8; g++) { v[g] = __expf(v[g] - m); ssum += v[g]; }
            float inv = 1.0f / ssum;
#pragma unroll
            for (int g = 0; g < 8; g++)
                sm[SM_S + (h * 8 + g) * 256 + p] = v[g] * inv;
        }
    }
    __syncthreads();

    // ---- GEMM2: out[o][p] = sum_k A[k][p] * P[k][o], 8 chunks of 32 outputs
    float* ob = out + (size_t)b * C * NPOS + n0;
    for (int oc = 0; oc < 8; oc++) {
        u64 c0[8], c1[8];
#pragma unroll
        for (int k = 0; k < 8; k++) { c0[k] = 0ull; c1[k] = 0ull; }
        int obase = oc * 32 + og * 16;
#pragma unroll 8
        for (int k = 0; k < 32; k++) {
            float a0 = sm[SM_S + k * 256 + j];
            float a1 = sm[SM_S + k * 256 + j + 128];
            u64 a0d = dup2(a0), a1d = dup2(a1);
            const ulonglong2* wq = reinterpret_cast<const ulonglong2*>(
                sm + SM_P + k * 256 + obase);
#pragma unroll
            for (int pr = 0; pr < 4; pr++) {
                ulonglong2 w = wq[pr];
                c0[pr * 2]     = ffma2(w.x, a0d, c0[pr * 2]);
                c0[pr * 2 + 1] = ffma2(w.y, a0d, c0[pr * 2 + 1]);
                c1[pr * 2]     = ffma2(w.x, a1d, c1[pr * 2]);
                c1[pr * 2 + 1] = ffma2(w.y, a1d, c1[pr * 2 + 1]);
            }
        }
#pragma unroll
        for (int oo = 0; oo < 8; oo++) {
            int o = obase + oo * 2;
            ob[(size_t)o * NPOS + j]             = lo2(c0[oo]);
            ob[(size_t)(o + 1) * NPOS + j]       = hi2(c0[oo]);
            ob[(size_t)o * NPOS + j + 128]       = lo2(c1[oo]);
            ob[(size_t)(o + 1) * NPOS + j + 128] = hi2(c1[oo]);
        }
    }
}

// ---------------------------------------------------------------------------
extern "C" void kernel_launch(void* const* d_in, const int* in_sizes, int n_in,
                              void* d_out, int out_size) {
    const float* x2     = (const float*)d_in[0];
    const float* x1_low = (const float*)d_in[1];
    const float* q_w    = (const float*)d_in[2];
    const float* k_w    = (const float*)d_in[3];
    const float* v_w    = (const float*)d_in[4];
    const float* dw_w   = (const float*)d_in[5];
    const float* proj_w = (const float*)d_in[6];
    const float* nq_w   = (const float*)d_in[7];
    const float* nq_b   = (const float*)d_in[8];
    const float* nkv_w  = (const float*)d_in[9];
    const float* nkv_b  = (const float*)d_in[10];
    float* out = (float*)d_out;

    cudaFuncSetAttribute(k_main, cudaFuncAttributeMaxDynamicSharedMemorySize,
                         SM_TOT * sizeof(float));

    k_tokens<<<512, 256>>>(x1_low, dw_w);
    k_kv<<<16, 256>>>(k_w, v_w, nkv_w, nkv_b);
    k_fold<<<2, 256>>>(q_w, proj_w);
    k_fold2<<<2, 32>>>(nq_w, nq_b);
    k_main<<<256, 256, SM_TOT * sizeof(float)>>>(x2, nq_w, out);
}

// round 4
// speedup vs baseline: 10.7101x; 4.0650x over previous
#include <cuda_runtime.h>
#include <math.h>

#define C 256
#define NPOS 32768
#define G 8
#define H 4

typedef unsigned long long u64;

// ---- scratch --------------------------------------------------------------
__device__ float g_tokens[2 * C * G];     // [b][c][g]
__device__ float g_K[2 * H * 64 * G];     // [b][h][d][g], pre-scaled by 1/8
__device__ float g_V[2 * H * G * 64];     // [b][h][g][d]
__device__ float g_Ms[2 * C * 32];        // [b][c][hg]  folded score matrix * nq_w
__device__ float g_P[2 * 32 * C];         // [b][hg][o]  folded output matrix
__device__ float g_cs[2 * 32];            // colsum of Ms*nq_w
__device__ float g_bias[2 * 32];          // Ms . nq_b

// ---- f32x2 helpers ----------------------------------------------------------
__device__ __forceinline__ u64 dup2(float a) {
    u64 r; asm("mov.b64 %0,{%1,%1};" : "=l"(r) : "f"(a)); return r;
}
__device__ __forceinline__ u64 pack2(float a, float b) {
    u64 r; asm("mov.b64 %0,{%1,%2};" : "=l"(r) : "f"(a), "f"(b)); return r;
}
__device__ __forceinline__ u64 ffma2(u64 a, u64 b, u64 c) {
    u64 d; asm("fma.rn.f32x2 %0,%1,%2,%3;" : "=l"(d) : "l"(a), "l"(b), "l"(c)); return d;
}
__device__ __forceinline__ u64 add2(u64 a, u64 b) {
    u64 d; asm("add.rn.f32x2 %0,%1,%2;" : "=l"(d) : "l"(a), "l"(b)); return d;
}
__device__ __forceinline__ float lo2(u64 v) { return __uint_as_float((unsigned)v); }
__device__ __forceinline__ float hi2(u64 v) { return __uint_as_float((unsigned)(v >> 32)); }

__device__ __forceinline__ void cpa16(unsigned s, const void* g) {
    asm volatile("cp.async.cg.shared.global [%0], [%1], 16;" :: "r"(s), "l"(g));
}
__device__ __forceinline__ void cpa_commit() { asm volatile("cp.async.commit_group;"); }
__device__ __forceinline__ void cpa_wait1() { asm volatile("cp.async.wait_group 1;"); }
__device__ __forceinline__ void cpa_wait0() { asm volatile("cp.async.wait_group 0;"); }

// ---------------------------------------------------------------------------
// pool 16^3 -> 2^3 + depthwise 3^3 conv (SAME) + residual
// ---------------------------------------------------------------------------
__global__ void k_tokens(const float* __restrict__ x1,
                         const float* __restrict__ dw_w) {
    int bc = blockIdx.x;               // b*256 + c
    int c = bc & 255;
    const float* xp = x1 + (size_t)bc * 4096;
    int tid = threadIdx.x;
    int w = tid >> 5, lane = tid & 31;
    int gz = w >> 2, gy = (w >> 1) & 1, gx = w & 1;
    float s = 0.f;
#pragma unroll
    for (int k = 0; k < 16; k++) {
        int e = lane + 32 * k;
        int lz = e >> 6, ly = (e >> 3) & 7, lx = e & 7;
        s += xp[(gz * 8 + lz) * 256 + (gy * 8 + ly) * 16 + (gx * 8 + lx)];
    }
#pragma unroll
    for (int off = 16; off; off >>= 1) s += __shfl_down_sync(0xffffffffu, s, off);
    __shared__ float pooled[8];
    if (lane == 0) pooled[w] = s * (1.0f / 512.0f);
    __syncthreads();
    if (tid < 8) {
        int z = tid >> 2, y = (tid >> 1) & 1, x = tid & 1;
        float acc = 0.f;
        for (int dz = -1; dz <= 1; dz++)
            for (int dy = -1; dy <= 1; dy++)
                for (int dx = -1; dx <= 1; dx++) {
                    int nz = z + dz, ny = y + dy, nx = x + dx;
                    if ((unsigned)nz < 2u && (unsigned)ny < 2u && (unsigned)nx < 2u)
                        acc += dw_w[c * 27 + (dz + 1) * 9 + (dy + 1) * 3 + (dx + 1)] *
                               pooled[nz * 4 + ny * 2 + nx];
                }
        g_tokens[bc * 8 + tid] = pooled[tid] + acc;
    }
}

// ---------------------------------------------------------------------------
// LN(tokens) over channels, K (prescaled), V — warp-per-output, coalesced
// ---------------------------------------------------------------------------
__global__ void k_kv(const float* __restrict__ k_w, const float* __restrict__ v_w,
                     const float* __restrict__ nkv_w, const float* __restrict__ nkv_b) {
    int bg = blockIdx.x;               // b*8 + g
    int b = bg >> 3, g = bg & 7;
    int tid = threadIdx.x;             // 256
    int w = tid >> 5, lane = tid & 31;
    __shared__ float tok[256], tk[256], red[16];
    __shared__ float uu, rstd;
    float t = g_tokens[(b * 256 + tid) * 8 + g];
    tok[tid] = t;
    float s1 = t, s2 = t * t;
#pragma unroll
    for (int off = 16; off; off >>= 1) {
        s1 += __shfl_down_sync(0xffffffffu, s1, off);
        s2 += __shfl_down_sync(0xffffffffu, s2, off);
    }
    if (lane == 0) { red[w] = s1; red[8 + w] = s2; }
    __syncthreads();
    if (tid == 0) {
        float a = 0.f, q = 0.f;
        for (int i = 0; i < 8; i++) { a += red[i]; q += red[8 + i]; }
        float u = a * (1.0f / 256.0f);
        float var = q * (1.0f / 256.0f) - u * u;
        uu = u; rstd = rsqrtf(var + 1e-6f);
    }
    __syncthreads();
    tk[tid] = (t - uu) * rstd * nkv_w[tid] + nkv_b[tid];
    __syncthreads();

    // warp w computes outputs o = w*32 .. w*32+31, lanes split c (coalesced)
    for (int oo = 0; oo < 32; oo++) {
        int o = w * 32 + oo;
        const float* kr = k_w + o * 256;
        const float* vr = v_w + o * 256;
        float pk = 0.f, pv = 0.f;
#pragma unroll
        for (int i = 0; i < 8; i++) {
            int c2 = lane + 32 * i;
            pk += kr[c2] * tk[c2];
            pv += vr[c2] * tok[c2];
        }
#pragma unroll
        for (int off = 16; off; off >>= 1) {
            pk += __shfl_down_sync(0xffffffffu, pk, off);
            pv += __shfl_down_sync(0xffffffffu, pv, off);
        }
        if (lane == 0) {
            int h = o >> 6, d = o & 63;
            g_K[((b * 4 + h) * 64 + d) * 8 + g] = pk * 0.125f;
            g_V[((b * 4 + h) * 8 + g) * 64 + d] = pv;
        }
    }
}

// ---------------------------------------------------------------------------
// foldA: Ms[c][hg] = (sum_d q_w[h*64+d,c] * K[h,d,g]) * nq_w[c]   (stored premul)
//        cs[hg]   = sum_c Ms_premul ;  bias[hg] = sum_c Ms_raw * nq_b[c]
// grid = 64 (b*32+hg), block = 256 (thread = c)
// ---------------------------------------------------------------------------
__global__ void k_foldA(const float* __restrict__ q_w,
                        const float* __restrict__ nq_w,
                        const float* __restrict__ nq_b) {
    int bhg = blockIdx.x;
    int b = bhg >> 5, hg = bhg & 31, h = hg >> 3, g = hg & 7;
    int t = threadIdx.x;
    __shared__ float kd[64];
    __shared__ float r1[8], r2[8];
    if (t < 64) kd[t] = g_K[((b * 4 + h) * 64 + t) * 8 + g];
    __syncthreads();
    float s = 0.f;
    const float* qp = q_w + (h * 64) * 256 + t;
#pragma unroll 8
    for (int d = 0; d < 64; d++) s += qp[d * 256] * kd[d];
    float sp = s * nq_w[t];
    float sb = s * nq_b[t];
    g_Ms[(b * 256 + t) * 32 + hg] = sp;
    // block reduce sp, sb
    float a1 = sp, a2 = sb;
#pragma unroll
    for (int off = 16; off; off >>= 1) {
        a1 += __shfl_down_sync(0xffffffffu, a1, off);
        a2 += __shfl_down_sync(0xffffffffu, a2, off);
    }
    int w = t >> 5, lane = t & 31;
    if (lane == 0) { r1[w] = a1; r2[w] = a2; }
    __syncthreads();
    if (t == 0) {
        float c1 = 0.f, c2 = 0.f;
        for (int i = 0; i < 8; i++) { c1 += r1[i]; c2 += r2[i]; }
        g_cs[b * 32 + hg] = c1;
        g_bias[b * 32 + hg] = c2;
    }
}

// ---------------------------------------------------------------------------
// foldB: P[hg][o] = sum_d proj_w[o, h*64+d] * V[h,g,d]
// grid = 64 (b*32+hg); warp-per-output-row, lane-split over d (coalesced)
// ---------------------------------------------------------------------------
__global__ void k_foldB(const float* __restrict__ proj_w) {
    int bhg = blockIdx.x;
    int b = bhg >> 5, hg = bhg & 31, h = hg >> 3, g = hg & 7;
    int tid = threadIdx.x;
    int w = tid >> 5, lane = tid & 31;
    __shared__ float vd[64];
    if (tid < 64) vd[tid] = g_V[((b * 4 + h) * 8 + g) * 64 + tid];
    __syncthreads();
    for (int oo = 0; oo < 32; oo++) {
        int o = w * 32 + oo;
        const float* pw = proj_w + o * 256 + h * 64;
        float p = pw[lane] * vd[lane] + pw[32 + lane] * vd[32 + lane];
#pragma unroll
        for (int off = 16; off; off >>= 1)
            p += __shfl_down_sync(0xffffffffu, p, off);
        if (lane == 0) g_P[b * 8192 + hg * 256 + o] = p;
    }
}

// ---------------------------------------------------------------------------
// main fused kernel: 256 positions/block, 256 threads, 2 blocks/SM.
// X staging: 16 chunks of 16 channels, double-buffered (2 x 4096 floats).
// Score buffer S reuses the X region (dead after GEMM1).
// ---------------------------------------------------------------------------
#define SM_MSP 0
#define SM_P   8192
#define SM_X   16384          /* 2 bufs x 4096 floats; also S[32][256] after GEMM1 */
#define SM_S   16384
#define SM_RED 24576          /* 512 u64 */
#define SM_US  25600
#define SM_RS  25856
#define SM_CSB 26112          /* cs[32] bias[32] */
#define SM_TOT 26176

__global__ void __launch_bounds__(256, 2) k_main(
    const float* __restrict__ x2, float* __restrict__ out) {
    extern __shared__ float sm[];
    int tid = threadIdx.x;
    int j = tid & 127, og = tid >> 7;
    int b = blockIdx.x >> 7;
    int n0 = (blockIdx.x & 127) * 256;

    const float* xb = x2 + (size_t)b * C * NPOS + n0;
    unsigned xs_u32 = (unsigned)__cvta_generic_to_shared(sm + SM_X);

    // prologue: chunk 0 (16 channels x 256 pos)
    {
#pragma unroll
        for (int it = 0; it < 4; it++) {
            int idx = tid + it * 256;
            int row = idx >> 6, col = idx & 63;
            cpa16(xs_u32 + (unsigned)(row * 1024 + col * 16),
                  xb + (size_t)row * NPOS + col * 4);
        }
        cpa_commit();
    }

    // load folded weights (L2-resident, shared across blocks)
    for (int i = tid; i < 8192; i += 256) {
        sm[SM_MSP + i] = g_Ms[b * 8192 + i];
        sm[SM_P + i]   = g_P[b * 8192 + i];
    }
    if (tid < 32) {
        sm[SM_CSB + tid]      = g_cs[b * 32 + tid];
        sm[SM_CSB + 32 + tid] = g_bias[b * 32 + tid];
    }

    u64 acc0[8], acc1[8], s1p = 0ull, s2p = 0ull;
#pragma unroll
    for (int k = 0; k < 8; k++) { acc0[k] = 0ull; acc1[k] = 0ull; }

    for (int ch = 0; ch < 16; ch++) {
        if (ch < 15) {
            const float* src = xb + (size_t)((ch + 1) * 16) * NPOS;
            unsigned dst = xs_u32 + ((unsigned)((ch + 1) & 1)) * 16384u;
#pragma unroll
            for (int it = 0; it < 4; it++) {
                int idx = tid + it * 256;
                int row = idx >> 6, col = idx & 63;
                cpa16(dst + (unsigned)(row * 1024 + col * 16),
                      src + (size_t)row * NPOS + col * 4);
            }
            cpa_commit();
            cpa_wait1();
        } else {
            cpa_wait0();
        }
        __syncthreads();

        const float* Xc = sm + SM_X + ((ch & 1) << 12);
        bool dostats = (og == (ch >> 3));
#pragma unroll
        for (int cl = 0; cl < 16; cl++) {
            float x0 = Xc[cl * 256 + j];
            float x1 = Xc[cl * 256 + j + 128];
            u64 x0d = dup2(x0), x1d = dup2(x1);
            const ulonglong2* wq = reinterpret_cast<const ulonglong2*>(
                sm + SM_MSP + (ch * 16 + cl) * 32 + og * 16);
#pragma unroll
            for (int pr = 0; pr < 4; pr++) {
                ulonglong2 w = wq[pr];
                acc0[pr * 2]     = ffma2(w.x, x0d, acc0[pr * 2]);
                acc0[pr * 2 + 1] = ffma2(w.y, x0d, acc0[pr * 2 + 1]);
                acc1[pr * 2]     = ffma2(w.x, x1d, acc1[pr * 2]);
                acc1[pr * 2 + 1] = ffma2(w.y, x1d, acc1[pr * 2 + 1]);
            }
            if (dostats) {
                u64 xp = pack2(x0, x1);
                s1p = add2(s1p, xp);
                s2p = ffma2(xp, xp, s2p);
            }
        }
        __syncthreads();
    }

    // ---- reduce LN stats (pos j in lo lane, pos j+128 in hi lane)
    u64* redm = reinterpret_cast<u64*>(sm + SM_RED);
    redm[(og * 128 + j) * 2]     = s1p;
    redm[(og * 128 + j) * 2 + 1] = s2p;
    __syncthreads();
    if (og == 0) {
        u64 s1t = add2(redm[j * 2], redm[(128 + j) * 2]);
        u64 s2t = add2(redm[j * 2 + 1], redm[(128 + j) * 2 + 1]);
        float u0 = lo2(s1t) * (1.0f / 256.0f), u1 = hi2(s1t) * (1.0f / 256.0f);
        float v0 = lo2(s2t) * (1.0f / 256.0f) - u0 * u0;
        float v1 = hi2(s2t) * (1.0f / 256.0f) - u1 * u1;
        sm[SM_US + j] = u0;       sm[SM_US + j + 128] = u1;
        sm[SM_RS + j] = rsqrtf(v0 + 1e-6f);
        sm[SM_RS + j + 128] = rsqrtf(v1 + 1e-6f);
    }
    __syncthreads();

    // ---- correct scores, write S[hg][pos] (reuses X region)
    {
        u64 nu0 = dup2(-sm[SM_US + j]);
        u64 nu1 = dup2(-sm[SM_US + j + 128]);
        u64 r0  = dup2(sm[SM_RS + j]);
        u64 r1  = dup2(sm[SM_RS + j + 128]);
        const u64* csb = reinterpret_cast<const u64*>(sm + SM_CSB);
#pragma unroll
        for (int oo = 0; oo < 8; oo++) {
            int o = og * 16 + oo * 2;
            u64 cs2 = csb[o >> 1];
            u64 b2  = csb[16 + (o >> 1)];
            u64 sc0 = ffma2(ffma2(cs2, nu0, acc0[oo]), r0, b2);
            u64 sc1 = ffma2(ffma2(cs2, nu1, acc1[oo]), r1, b2);
            sm[SM_S + o * 256 + j]             = lo2(sc0);
            sm[SM_S + (o + 1) * 256 + j]       = hi2(sc0);
            sm[SM_S + o * 256 + j + 128]       = lo2(sc1);
            sm[SM_S + (o + 1) * 256 + j + 128] = hi2(sc1);
        }
    }
    __syncthreads();

    // ---- softmax: thread = position, 4 heads x 8 keys
    {
        int p = tid;
#pragma unroll
        for (int h = 0; h < 4; h++) {
            float v[8], m = -1e30f;
#pragma unroll
            for (int g = 0; g < 8; g++) {
                v[g] = sm[SM_S + (h * 8 + g) * 256 + p];
                m = fmaxf(m, v[g]);
            }
            float ssum = 0.f;
#pragma unroll
            for (int g = 0; g < 8; g++) { v[g] = __expf(v[g] - m); ssum += v[g]; }
            float inv = 1.0f / ssum;
#pragma unroll
            for (int g = 0; g < 8; g++)
                sm[SM_S + (h * 8 + g) * 256 + p] = v[g] * inv;
        }
    }
    __syncthreads();

    // ---- GEMM2: out[o][p] = sum_k A[k][p] * P[k][o]
    float* ob = out + (size_t)b * C * NPOS + n0;
    for (int oc = 0; oc < 8; oc++) {
        u64 c0[8], c1[8];
#pragma unroll
        for (int k = 0; k < 8; k++) { c0[k] = 0ull; c1[k] = 0ull; }
        int obase = oc * 32 + og * 16;
#pragma unroll 8
        for (int k = 0; k < 32; k++) {
            float a0 = sm[SM_S + k * 256 + j];
            float a1 = sm[SM_S + k * 256 + j + 128];
            u64 a0d = dup2(a0), a1d = dup2(a1);
            const ulonglong2* wq = reinterpret_cast<const ulonglong2*>(
                sm + SM_P + k * 256 + obase);
#pragma unroll
            for (int pr = 0; pr < 4; pr++) {
                ulonglong2 w = wq[pr];
                c0[pr * 2]     = ffma2(w.x, a0d, c0[pr * 2]);
                c0[pr * 2 + 1] = ffma2(w.y, a0d, c0[pr * 2 + 1]);
                c1[pr * 2]     = ffma2(w.x, a1d, c1[pr * 2]);
                c1[pr * 2 + 1] = ffma2(w.y, a1d, c1[pr * 2 + 1]);
            }
        }
#pragma unroll
        for (int oo = 0; oo < 8; oo++) {
            int o = obase + oo * 2;
            ob[(size_t)o * NPOS + j]             = lo2(c0[oo]);
            ob[(size_t)(o + 1) * NPOS + j]       = hi2(c0[oo]);
            ob[(size_t)o * NPOS + j + 128]       = lo2(c1[oo]);
            ob[(size_t)(o + 1) * NPOS + j + 128] = hi2(c1[oo]);
        }
    }
}

// ---------------------------------------------------------------------------
extern "C" void kernel_launch(void* const* d_in, const int* in_sizes, int n_in,
                              void* d_out, int out_size) {
    const float* x2     = (const float*)d_in[0];
    const float* x1_low = (const float*)d_in[1];
    const float* q_w    = (const float*)d_in[2];
    const float* k_w    = (const float*)d_in[3];
    const float* v_w    = (const float*)d_in[4];
    const float* dw_w   = (const float*)d_in[5];
    const float* proj_w = (const float*)d_in[6];
    const float* nq_w   = (const float*)d_in[7];
    const float* nq_b   = (const float*)d_in[8];
    const float* nkv_w  = (const float*)d_in[9];
    const float* nkv_b  = (const float*)d_in[10];
    float* out = (float*)d_out;

    cudaFuncSetAttribute(k_main, cudaFuncAttributeMaxDynamicSharedMemorySize,
                         SM_TOT * sizeof(float));

    k_tokens<<<512, 256>>>(x1_low, dw_w);
    k_kv<<<16, 256>>>(k_w, v_w, nkv_w, nkv_b);
    k_foldA<<<64, 256>>>(q_w, nq_w, nq_b);
    k_foldB<<<64, 256>>>(proj_w);
    k_main<<<256, 256, SM_TOT * sizeof(float)>>>(x2, out);
}